// round 14
// baseline (speedup 1.0000x reference)
#include <cuda_runtime.h>
#include <cuda_fp16.h>
#include <cstdint>
#include <math.h>
#include <float.h>

#define MDIM   4096
#define KDIM   1024
#define VOCABN 32000
#define NBITS  15
#define NWORDS (VOCABN / 32)
#define MAXCAND 128

// ---------------- scratch ----------------------------------------------------
__device__ __half g_Ah[(size_t)MDIM * KDIM];
__device__ __half g_Bh[(size_t)VOCABN * KDIM];
__device__ uint32_t g_rowmax[MDIM];     // monotone-uint encoded fp32 row max

__device__ __forceinline__ uint32_t smem_u32(const void* p) {
    uint32_t a;
    asm("{ .reg .u64 t; cvta.to.shared.u64 t, %1; cvt.u32.u64 %0, t; }"
        : "=r"(a) : "l"(p));
    return a;
}
#define SW128(o) ((o) ^ (((o) >> 3) & 0x70))

__device__ __forceinline__ uint32_t fkey(float f) {
    uint32_t u = __float_as_uint(f);
    return (u & 0x80000000u) ? ~u : (u | 0x80000000u);
}
__device__ __forceinline__ float fdec(uint32_t k) {
    return __uint_as_float((k & 0x80000000u) ? (k & 0x7fffffffu) : ~k);
}

// ---------------- init rowmax ------------------------------------------------
__global__ __launch_bounds__(256) void init_rowmax_kernel() {
    g_rowmax[blockIdx.x * 256 + threadIdx.x] = fkey(-FLT_MAX);
}

// ---------------- convert kernels (f32 -> fp16) ------------------------------
__global__ __launch_bounds__(256) void conv_A_kernel(const float* __restrict__ src) {
    int i = blockIdx.x * 256 + threadIdx.x;
    float4 v = ((const float4*)src)[i];
    ushort4 h4;
    h4.x = __half_as_ushort(__float2half_rn(v.x));
    h4.y = __half_as_ushort(__float2half_rn(v.y));
    h4.z = __half_as_ushort(__float2half_rn(v.z));
    h4.w = __half_as_ushort(__float2half_rn(v.w));
    ((ushort4*)g_Ah)[i] = h4;
}
__global__ __launch_bounds__(256) void conv_B_kernel(const float* __restrict__ src) {
    int i = blockIdx.x * 256 + threadIdx.x;
    float4 v = ((const float4*)src)[i];
    ushort4 h4;
    h4.x = __half_as_ushort(__float2half_rn(v.x));
    h4.y = __half_as_ushort(__float2half_rn(v.y));
    h4.z = __half_as_ushort(__float2half_rn(v.z));
    h4.w = __half_as_ushort(__float2half_rn(v.w));
    ((ushort4*)g_Bh)[i] = h4;
}

// ---------------- embed: gather + bit combo ---------------------------------
__global__ __launch_bounds__(256) void embed_kernel(
    const int* __restrict__ ids, const float* __restrict__ weight,
    const float* __restrict__ weight_bit,
    float* __restrict__ out_id, float* __restrict__ out_bit)
{
    const int t = blockIdx.x;
    const int id = ids[t];
    const int d = threadIdx.x * 4;
    float4 w = *(const float4*)(weight + (size_t)id * KDIM + d);
    *(float4*)(out_id + (size_t)t * KDIM + d) = w;
    float4 acc = make_float4(0.f, 0.f, 0.f, 0.f);
#pragma unroll
    for (int j = 0; j < NBITS; j++) {
        const float s = ((id >> (NBITS - 1 - j)) & 1) ? 1.0f : -1.0f;
        float4 wb = *(const float4*)(weight_bit + j * KDIM + d);
        acc.x = fmaf(s, wb.x, acc.x); acc.y = fmaf(s, wb.y, acc.y);
        acc.z = fmaf(s, wb.z, acc.z); acc.w = fmaf(s, wb.w, acc.w);
    }
    *(float4*)(out_bit + (size_t)t * KDIM + d) = acc;
}

// ---------------- fp16 GEMM, f16 accumulators + per-kt fp32 drain ------------
// C[4096,32000] = Ah @ Bh^T. CTA 128x128, 256 threads, warp tile 64x32
// (2Mx4N), BK=64, 3-stage cp.async. Each kt accumulates 4 chained k16 MMAs
// in f16 (testing the f16-acc-rate hypothesis), drains to fp32 regs per kt.
#define BM 128
#define BN 128
#define BK 64
#define NSTAGE 3
#define TILE_A (BM * BK * 2)            // 16 KB
#define TILE_Bt (BN * BK * 2)           // 16 KB
#define OFF_B TILE_A
#define STAGE_B (TILE_A + TILE_Bt)      // 32 KB
#define GEMM_SMEM (NSTAGE * STAGE_B)    // 96 KB

#define CP16(dst, src) \
    asm volatile("cp.async.cg.shared.global [%0], [%1], 16;" \
                 :: "r"(dst), "l"(src) : "memory")
#define LDSM4(r0, r1, r2, r3, a) \
    asm volatile("ldmatrix.sync.aligned.m8n8.x4.shared.b16 {%0,%1,%2,%3}, [%4];" \
                 : "=r"(r0), "=r"(r1), "=r"(r2), "=r"(r3) : "r"(a))
// f16 accumulator variant: D,C are 2 x f16x2 regs
#define MMA16816H(d, a, b0, b1) \
    asm volatile("mma.sync.aligned.m16n8k16.row.col.f16.f16.f16.f16 " \
                 "{%0,%1}, {%2,%3,%4,%5}, {%6,%7}, {%0,%1};" \
                 : "+r"((d)[0]), "+r"((d)[1]) \
                 : "r"((a)[0]), "r"((a)[1]), "r"((a)[2]), "r"((a)[3]), \
                   "r"(b0), "r"(b1))

__global__ __launch_bounds__(256, 1) void gemm_kernel(float* __restrict__ C)
{
    extern __shared__ char smem[];
    const uint32_t sb = smem_u32(smem);
    const int tid = threadIdx.x, wid = tid >> 5, lane = tid & 31;
    const int bm = blockIdx.x * BM, bn = blockIdx.y * BN;
    const int wm = (wid & 1) * 64;      // 2 warps in M
    const int wn = (wid >> 1) * 32;     // 4 warps in N

    const __half* gAh = g_Ah + (size_t)bm * KDIM;
    const __half* gBh = g_Bh + (size_t)bn * KDIM;

    const int NK = KDIM / BK;           // 16

    auto load_stage = [&](int kt, int stg) {
        const uint32_t base = sb + stg * STAGE_B;
        const int ke = kt * BK;
#pragma unroll
        for (int i = 0; i < 4; i++) {
            const int chunk = i * 256 + tid;
            const int row = chunk >> 3;
            const int kc = chunk & 7;
            const uint32_t d = SW128(row * 128 + kc * 16);
            const size_t so = (size_t)row * KDIM + ke + kc * 8;
            CP16(base + d,         gAh + so);
            CP16(base + OFF_B + d, gBh + so);
        }
        asm volatile("cp.async.commit_group;" ::: "memory");
    };

    load_stage(0, 0);
    load_stage(1, 1);

    float acc[4][4][4] = {};            // fp32 running sums (64 regs)

    const int lrow = lane & 15;
    const int lkb  = (lane >> 4) * 16;
    int offA[4], offB[2];
#pragma unroll
    for (int mt = 0; mt < 4; mt++) offA[mt] = (wm + mt * 16 + lrow) * 128 + lkb;
#pragma unroll
    for (int nt = 0; nt < 2; nt++) offB[nt] = (wn + nt * 16 + lrow) * 128 + lkb;

    int stg = 0;
    for (int kt = 0; kt < NK; kt++) {
        asm volatile("cp.async.wait_group 1;" ::: "memory");
        __syncthreads();
        if (kt + 2 < NK) {
            int s2 = stg + 2; if (s2 >= NSTAGE) s2 -= NSTAGE;
            load_stage(kt + 2, s2);
        }
        const uint32_t base = sb + stg * STAGE_B;

        uint32_t hacc[4][4][2];         // f16x2 accumulators for this kt
#pragma unroll
        for (int mt = 0; mt < 4; mt++)
#pragma unroll
            for (int j = 0; j < 4; j++) { hacc[mt][j][0] = 0u; hacc[mt][j][1] = 0u; }

#pragma unroll
        for (int ks = 0; ks < 4; ks++) {
            uint32_t ah[4][4];
#pragma unroll
            for (int mt = 0; mt < 4; mt++) {
                const uint32_t a = base + SW128(offA[mt] + ks * 32);
                LDSM4(ah[mt][0], ah[mt][1], ah[mt][2], ah[mt][3], a);
            }
            uint32_t b[2][4];
#pragma unroll
            for (int nt = 0; nt < 2; nt++) {
                const uint32_t ba = base + SW128(offB[nt] + ks * 32);
                LDSM4(b[nt][0], b[nt][1], b[nt][2], b[nt][3], ba + OFF_B);
            }
#pragma unroll
            for (int mt = 0; mt < 4; mt++)
#pragma unroll
                for (int nt = 0; nt < 2; nt++) {
                    MMA16816H(hacc[mt][2 * nt + 0], ah[mt], b[nt][0], b[nt][2]);
                    MMA16816H(hacc[mt][2 * nt + 1], ah[mt], b[nt][1], b[nt][3]);
                }
        }
        // drain f16 chunk sums into fp32 accumulators
#pragma unroll
        for (int mt = 0; mt < 4; mt++)
#pragma unroll
            for (int j = 0; j < 4; j++) {
                float2 f0 = __half22float2(*(__half2*)&hacc[mt][j][0]);
                float2 f1 = __half22float2(*(__half2*)&hacc[mt][j][1]);
                acc[mt][j][0] += f0.x; acc[mt][j][1] += f0.y;
                acc[mt][j][2] += f1.x; acc[mt][j][3] += f1.y;
            }
        if (++stg >= NSTAGE) stg = 0;
    }

    // epilogue: stores + folded per-row max (atomicMax, order-independent)
    const int er = lane >> 2, ec = (lane & 3) * 2;
#pragma unroll
    for (int mt = 0; mt < 4; mt++) {
        float r0 = -FLT_MAX, r1 = -FLT_MAX;
#pragma unroll
        for (int j = 0; j < 4; j++) {
            float* c0 = C + (size_t)(bm + wm + mt * 16 + er) * VOCABN
                          + bn + wn + j * 8 + ec;
            *(float2*)c0 = make_float2(acc[mt][j][0], acc[mt][j][1]);
            float* c1 = c0 + (size_t)8 * VOCABN;
            *(float2*)c1 = make_float2(acc[mt][j][2], acc[mt][j][3]);
            r0 = fmaxf(r0, fmaxf(acc[mt][j][0], acc[mt][j][1]));
            r1 = fmaxf(r1, fmaxf(acc[mt][j][2], acc[mt][j][3]));
        }
        r0 = fmaxf(r0, __shfl_xor_sync(0xffffffffu, r0, 1));
        r0 = fmaxf(r0, __shfl_xor_sync(0xffffffffu, r0, 2));
        r1 = fmaxf(r1, __shfl_xor_sync(0xffffffffu, r1, 1));
        r1 = fmaxf(r1, __shfl_xor_sync(0xffffffffu, r1, 2));
        if ((lane & 3) == 0) {
            atomicMax(&g_rowmax[bm + wm + mt * 16 + er],     fkey(r0));
            atomicMax(&g_rowmax[bm + wm + mt * 16 + er + 8], fkey(r1));
        }
    }
}

// ---------------- softmax (single logit pass) + exact candidate dots --------
__global__ __launch_bounds__(256) void softmax_bits_kernel(
    const float* __restrict__ logit, const float* __restrict__ tensor,
    const float* __restrict__ weight, float* __restrict__ logit_w)
{
    const int row = blockIdx.x;
    const int tid = threadIdx.x;
    const int lane = tid & 31, wid = tid >> 5;
    const float4* x4 = (const float4*)(logit + (size_t)row * VOCABN);

    __shared__ uint32_t bitmap[NWORDS];
    __shared__ int s_vcand[MAXCAND];
    __shared__ int s_count;
    __shared__ float s_part[8];
    __shared__ float s_e[MAXCAND];
    __shared__ float sfin[16];

    for (int i = tid; i < NWORDS; i += 256) bitmap[i] = 0u;
    __syncthreads();

    const float mm = fdec(g_rowmax[row]);
    const float thr = mm - 20.0f;

    for (int i = tid; i < VOCABN / 4; i += 256) {
        float4 v = x4[i];
        const float c[4] = {v.x, v.y, v.z, v.w};
#pragma unroll
        for (int j = 0; j < 4; j++)
            if (c[j] > thr) {
                const int vv = i * 4 + j;
                atomicOr(&bitmap[vv >> 5], 1u << (vv & 31));
            }
    }
    __syncthreads();

    if (wid == 0) {
        const int w0 = lane * 32;
        int cnt = 0;
        for (int w = w0; w < w0 + 32 && w < NWORDS; w++) cnt += __popc(bitmap[w]);
        int pre = cnt;
#pragma unroll
        for (int o = 1; o < 32; o <<= 1) {
            int n = __shfl_up_sync(0xffffffffu, pre, o);
            if (lane >= o) pre += n;
        }
        if (lane == 31) s_count = (pre < MAXCAND) ? pre : MAXCAND;
        int idx = pre - cnt;
        for (int w = w0; w < w0 + 32 && w < NWORDS; w++) {
            uint32_t bits = bitmap[w];
            while (bits) {
                const int b = __ffs(bits) - 1;
                bits &= bits - 1;
                if (idx < MAXCAND) s_vcand[idx] = w * 32 + b;
                idx++;
            }
        }
    }
    __syncthreads();
    const int cnt = s_count;

    const float4 ta = ((const float4*)(tensor + (size_t)row * KDIM))[tid];
    for (int c = 0; c < cnt; c++) {
        const int vv = s_vcand[c];
        const float4 wb = ((const float4*)(weight + (size_t)vv * KDIM))[tid];
        float p = fmaf(ta.x, wb.x, fmaf(ta.y, wb.y, fmaf(ta.z, wb.z, ta.w * wb.w)));
#pragma unroll
        for (int o = 16; o; o >>= 1) p += __shfl_xor_sync(0xffffffffu, p, o);
        if (lane == 0) s_part[wid] = p;
        __syncthreads();
        if (tid == 0) {
            float s = 0.f;
#pragma unroll
            for (int w = 0; w < 8; w++) s += s_part[w];
            s_e[c] = __expf(s - mm);
        }
        __syncthreads();
    }

    if (tid < 16) {
        float s = 0.f;
        for (int c = 0; c < cnt; c++) {
            const float e = s_e[c];
            if (tid == NBITS) s += e;
            else if ((s_vcand[c] >> (NBITS - 1 - tid)) & 1) s += e;
        }
        sfin[tid] = s;
    }
    __syncthreads();
    if (tid < NBITS) {
        const float Zt = sfin[NBITS];
        logit_w[(size_t)row * NBITS + tid] = (2.f * sfin[tid] - Zt) / Zt;
    }
}

// ---------------- launch ----------------------------------------------------
extern "C" void kernel_launch(void* const* d_in, const int* in_sizes, int n_in,
                              void* d_out, int out_size)
{
    const int*   ids        = (const int*)  d_in[0];
    const float* tensor     = (const float*)d_in[1];
    const float* weight     = (const float*)d_in[2];
    const float* weight_bit = (const float*)d_in[3];

    float* out       = (float*)d_out;
    float* out_id    = out;
    float* out_bit   = out + (size_t)MDIM * KDIM;
    float* out_logit = out + (size_t)2 * MDIM * KDIM;
    float* out_lw    = out_logit + (size_t)MDIM * VOCABN;

    cudaFuncSetAttribute(gemm_kernel,
                         cudaFuncAttributeMaxDynamicSharedMemorySize, GEMM_SMEM);

    init_rowmax_kernel<<<MDIM / 256, 256>>>();
    embed_kernel<<<MDIM, 256>>>(ids, weight, weight_bit, out_id, out_bit);
    conv_A_kernel<<<MDIM * KDIM / 1024, 256>>>(tensor);
    conv_B_kernel<<<VOCABN * KDIM / 1024, 256>>>(weight);

    dim3 grid(MDIM / BM, VOCABN / BN);  // M fastest -> B-slice L2 reuse
    gemm_kernel<<<grid, 256, GEMM_SMEM>>>(out_logit);

    softmax_bits_kernel<<<MDIM, 256>>>(out_logit, tensor, weight, out_lw);
}

// round 15
// speedup vs baseline: 1.1601x; 1.1601x over previous
#include <cuda_runtime.h>
#include <cuda_fp16.h>
#include <cstdint>
#include <math.h>
#include <float.h>

#define MDIM   4096
#define KDIM   1024
#define VOCABN 32000
#define NBITS  15
#define NWORDS (VOCABN / 32)            // 1000
#define MAXCAND 256

// ---------------- scratch ----------------------------------------------------
__device__ __half g_Ah[(size_t)MDIM * KDIM];
__device__ __half g_Bh[(size_t)VOCABN * KDIM];
__device__ uint32_t g_rowmax[MDIM];                 // monotone-uint fp32 row max
__device__ uint32_t g_bmap[(size_t)MDIM * NWORDS];  // candidate bitmap (16 MB)

__device__ __forceinline__ uint32_t smem_u32(const void* p) {
    uint32_t a;
    asm("{ .reg .u64 t; cvta.to.shared.u64 t, %1; cvt.u32.u64 %0, t; }"
        : "=r"(a) : "l"(p));
    return a;
}
#define SW128(o) ((o) ^ (((o) >> 3) & 0x70))

__device__ __forceinline__ uint32_t fkey(float f) {
    uint32_t u = __float_as_uint(f);
    return (u & 0x80000000u) ? ~u : (u | 0x80000000u);
}
__device__ __forceinline__ float fdec(uint32_t k) {
    return __uint_as_float((k & 0x80000000u) ? (k & 0x7fffffffu) : ~k);
}

// ---------------- init: zero bitmap + rowmax ---------------------------------
__global__ __launch_bounds__(256) void init_kernel() {
    const size_t i = (size_t)blockIdx.x * 256 + threadIdx.x;
    if (i < (size_t)MDIM * NWORDS) g_bmap[i] = 0u;
    if (i < MDIM) g_rowmax[i] = fkey(-FLT_MAX);
}

// ---------------- merged convert (f32 -> fp16) -------------------------------
#define NA_F4 (MDIM * KDIM / 4)
__global__ __launch_bounds__(256) void conv_kernel(
    const float* __restrict__ srcA, const float* __restrict__ srcB)
{
    const int i = blockIdx.x * 256 + threadIdx.x;
    const bool isA = (i < NA_F4);
    const int j = isA ? i : i - NA_F4;
    float4 v = isA ? ((const float4*)srcA)[j] : ((const float4*)srcB)[j];
    ushort4 h4;
    h4.x = __half_as_ushort(__float2half_rn(v.x));
    h4.y = __half_as_ushort(__float2half_rn(v.y));
    h4.z = __half_as_ushort(__float2half_rn(v.z));
    h4.w = __half_as_ushort(__float2half_rn(v.w));
    if (isA) ((ushort4*)g_Ah)[j] = h4; else ((ushort4*)g_Bh)[j] = h4;
}

// ---------------- embed: gather + bit combo ---------------------------------
__global__ __launch_bounds__(256) void embed_kernel(
    const int* __restrict__ ids, const float* __restrict__ weight,
    const float* __restrict__ weight_bit,
    float* __restrict__ out_id, float* __restrict__ out_bit)
{
    const int t = blockIdx.x;
    const int id = ids[t];
    const int d = threadIdx.x * 4;
    float4 w = *(const float4*)(weight + (size_t)id * KDIM + d);
    *(float4*)(out_id + (size_t)t * KDIM + d) = w;
    float4 acc = make_float4(0.f, 0.f, 0.f, 0.f);
#pragma unroll
    for (int j = 0; j < NBITS; j++) {
        const float s = ((id >> (NBITS - 1 - j)) & 1) ? 1.0f : -1.0f;
        float4 wb = *(const float4*)(weight_bit + j * KDIM + d);
        acc.x = fmaf(s, wb.x, acc.x); acc.y = fmaf(s, wb.y, acc.y);
        acc.z = fmaf(s, wb.z, acc.z); acc.w = fmaf(s, wb.w, acc.w);
    }
    *(float4*)(out_bit + (size_t)t * KDIM + d) = acc;
}

// ---------------- fp16 GEMM (fp32 acc) + marking epilogue --------------------
// C[4096,32000] = Ah @ Bh^T. CTA 128x128, 256 threads, warp tile 64x32
// (2Mx4N), BK=64, 3-stage cp.async, 2 CTAs/SM. Epilogue: per-row atomicMax
// running max; mark candidates (logit > running-20) in global bitmap —
// guaranteed superset of the final candidate set (running <= final max).
#define BM 128
#define BN 128
#define BK 64
#define NSTAGE 3
#define TILE_A (BM * BK * 2)
#define TILE_Bt (BN * BK * 2)
#define OFF_B TILE_A
#define STAGE_B (TILE_A + TILE_Bt)      // 32 KB
#define GEMM_SMEM (NSTAGE * STAGE_B)    // 96 KB

#define CP16(dst, src) \
    asm volatile("cp.async.cg.shared.global [%0], [%1], 16;" \
                 :: "r"(dst), "l"(src) : "memory")
#define LDSM4(r0, r1, r2, r3, a) \
    asm volatile("ldmatrix.sync.aligned.m8n8.x4.shared.b16 {%0,%1,%2,%3}, [%4];" \
                 : "=r"(r0), "=r"(r1), "=r"(r2), "=r"(r3) : "r"(a))
#define MMA16816(d, a, b0, b1) \
    asm volatile("mma.sync.aligned.m16n8k16.row.col.f32.f16.f16.f32 " \
                 "{%0,%1,%2,%3}, {%4,%5,%6,%7}, {%8,%9}, {%0,%1,%2,%3};" \
                 : "+f"((d)[0]), "+f"((d)[1]), "+f"((d)[2]), "+f"((d)[3]) \
                 : "r"((a)[0]), "r"((a)[1]), "r"((a)[2]), "r"((a)[3]), \
                   "r"(b0), "r"(b1))

__global__ __launch_bounds__(256, 2) void gemm_kernel(float* __restrict__ C)
{
    extern __shared__ char smem[];
    const uint32_t sb = smem_u32(smem);
    const int tid = threadIdx.x, wid = tid >> 5, lane = tid & 31;
    const int bm = blockIdx.x * BM, bn = blockIdx.y * BN;
    const int wm = (wid & 1) * 64;
    const int wn = (wid >> 1) * 32;

    const __half* gAh = g_Ah + (size_t)bm * KDIM;
    const __half* gBh = g_Bh + (size_t)bn * KDIM;

    const int NK = KDIM / BK;

    auto load_stage = [&](int kt, int stg) {
        const uint32_t base = sb + stg * STAGE_B;
        const int ke = kt * BK;
#pragma unroll
        for (int i = 0; i < 4; i++) {
            const int chunk = i * 256 + tid;
            const int row = chunk >> 3;
            const int kc = chunk & 7;
            const uint32_t d = SW128(row * 128 + kc * 16);
            const size_t so = (size_t)row * KDIM + ke + kc * 8;
            CP16(base + d,         gAh + so);
            CP16(base + OFF_B + d, gBh + so);
        }
        asm volatile("cp.async.commit_group;" ::: "memory");
    };

    load_stage(0, 0);
    load_stage(1, 1);

    float acc[4][4][4] = {};

    const int lrow = lane & 15;
    const int lkb  = (lane >> 4) * 16;
    int offA[4], offB[2];
#pragma unroll
    for (int mt = 0; mt < 4; mt++) offA[mt] = (wm + mt * 16 + lrow) * 128 + lkb;
#pragma unroll
    for (int nt = 0; nt < 2; nt++) offB[nt] = (wn + nt * 16 + lrow) * 128 + lkb;

    int stg = 0;
    for (int kt = 0; kt < NK; kt++) {
        asm volatile("cp.async.wait_group 1;" ::: "memory");
        __syncthreads();
        if (kt + 2 < NK) {
            int s2 = stg + 2; if (s2 >= NSTAGE) s2 -= NSTAGE;
            load_stage(kt + 2, s2);
        }
        const uint32_t base = sb + stg * STAGE_B;

#pragma unroll
        for (int ks = 0; ks < 4; ks++) {
            uint32_t ah[4][4];
#pragma unroll
            for (int mt = 0; mt < 4; mt++) {
                const uint32_t a = base + SW128(offA[mt] + ks * 32);
                LDSM4(ah[mt][0], ah[mt][1], ah[mt][2], ah[mt][3], a);
            }
            uint32_t b[2][4];
#pragma unroll
            for (int nt = 0; nt < 2; nt++) {
                const uint32_t ba = base + SW128(offB[nt] + ks * 32);
                LDSM4(b[nt][0], b[nt][1], b[nt][2], b[nt][3], ba + OFF_B);
            }
#pragma unroll
            for (int mt = 0; mt < 4; mt++)
#pragma unroll
                for (int nt = 0; nt < 2; nt++) {
                    MMA16816(acc[mt][2 * nt + 0], ah[mt], b[nt][0], b[nt][2]);
                    MMA16816(acc[mt][2 * nt + 1], ah[mt], b[nt][1], b[nt][3]);
                }
        }
        if (++stg >= NSTAGE) stg = 0;
    }

    // epilogue: stores + running row max + candidate marking
    const int er = lane >> 2, ec = (lane & 3) * 2;
#pragma unroll
    for (int mt = 0; mt < 4; mt++) {
        const int row0 = bm + wm + mt * 16 + er;
        const int row1 = row0 + 8;
        float r0 = -FLT_MAX, r1 = -FLT_MAX;
#pragma unroll
        for (int j = 0; j < 4; j++) {
            float* c0 = C + (size_t)row0 * VOCABN + bn + wn + j * 8 + ec;
            *(float2*)c0 = make_float2(acc[mt][j][0], acc[mt][j][1]);
            float* c1 = C + (size_t)row1 * VOCABN + bn + wn + j * 8 + ec;
            *(float2*)c1 = make_float2(acc[mt][j][2], acc[mt][j][3]);
            r0 = fmaxf(r0, fmaxf(acc[mt][j][0], acc[mt][j][1]));
            r1 = fmaxf(r1, fmaxf(acc[mt][j][2], acc[mt][j][3]));
        }
        r0 = fmaxf(r0, __shfl_xor_sync(0xffffffffu, r0, 1));
        r0 = fmaxf(r0, __shfl_xor_sync(0xffffffffu, r0, 2));
        r1 = fmaxf(r1, __shfl_xor_sync(0xffffffffu, r1, 1));
        r1 = fmaxf(r1, __shfl_xor_sync(0xffffffffu, r1, 2));
        uint32_t run0 = 0u, run1 = 0u;
        if ((lane & 3) == 0) {
            uint32_t o0 = atomicMax(&g_rowmax[row0], fkey(r0));
            uint32_t o1 = atomicMax(&g_rowmax[row1], fkey(r1));
            run0 = (o0 > fkey(r0)) ? o0 : fkey(r0);
            run1 = (o1 > fkey(r1)) ? o1 : fkey(r1);
        }
        run0 = __shfl_sync(0xffffffffu, run0, lane & ~3);
        run1 = __shfl_sync(0xffffffffu, run1, lane & ~3);
        const float t0 = fdec(run0) - 20.0f;
        const float t1 = fdec(run1) - 20.0f;
#pragma unroll
        for (int j = 0; j < 4; j++) {
            const int col = bn + wn + j * 8 + ec;
            if (acc[mt][j][0] > t0)
                atomicOr(&g_bmap[(size_t)row0 * NWORDS + (col >> 5)], 1u << (col & 31));
            if (acc[mt][j][1] > t0)
                atomicOr(&g_bmap[(size_t)row0 * NWORDS + ((col + 1) >> 5)], 1u << ((col + 1) & 31));
            if (acc[mt][j][2] > t1)
                atomicOr(&g_bmap[(size_t)row1 * NWORDS + (col >> 5)], 1u << (col & 31));
            if (acc[mt][j][3] > t1)
                atomicOr(&g_bmap[(size_t)row1 * NWORDS + ((col + 1) >> 5)], 1u << ((col + 1) & 31));
        }
    }
}

// ---------------- softmax from bitmap + exact candidate dots ----------------
// Reads only the candidate bitmap (4 KB/row), re-filters marked entries by
// stored logit > final max - 20 (deterministic), exact fp32 dot per survivor.
__global__ __launch_bounds__(256) void softmax_bits_kernel(
    const float* __restrict__ logit, const float* __restrict__ tensor,
    const float* __restrict__ weight, float* __restrict__ logit_w)
{
    const int row = blockIdx.x;
    const int tid = threadIdx.x;
    const int lane = tid & 31, wid = tid >> 5;

    __shared__ int s_vcand[MAXCAND];
    __shared__ int s_count;
    __shared__ float s_part[8];
    __shared__ float s_e[MAXCAND];
    __shared__ float sfin[16];

    const float mm = fdec(g_rowmax[row]);
    const float thr = mm - 20.0f;
    const uint32_t* bmap = g_bmap + (size_t)row * NWORDS;

    // warp 0: compact marked bits (ascending vv, deterministic given bitmap)
    if (wid == 0) {
        const int w0 = lane * 32;                 // 32 words per lane (1000 total)
        int cnt = 0;
        for (int w = w0; w < w0 + 32 && w < NWORDS; w++) cnt += __popc(bmap[w]);
        int pre = cnt;
#pragma unroll
        for (int o = 1; o < 32; o <<= 1) {
            int n = __shfl_up_sync(0xffffffffu, pre, o);
            if (lane >= o) pre += n;
        }
        if (lane == 31) s_count = (pre < MAXCAND) ? pre : MAXCAND;
        int idx = pre - cnt;
        for (int w = w0; w < w0 + 32 && w < NWORDS; w++) {
            uint32_t bits = bmap[w];
            while (bits) {
                const int b = __ffs(bits) - 1;
                bits &= bits - 1;
                if (idx < MAXCAND) s_vcand[idx] = w * 32 + b;
                idx++;
            }
        }
    }
    __syncthreads();
    const int cnt = s_count;

    // cooperative exact dots for survivors of the deterministic re-filter
    const float4 ta = ((const float4*)(tensor + (size_t)row * KDIM))[tid];
    for (int c = 0; c < cnt; c++) {
        const int vv = s_vcand[c];
        const float lg = logit[(size_t)row * VOCABN + vv];  // broadcast load
        if (lg > thr) {
            const float4 wb = ((const float4*)(weight + (size_t)vv * KDIM))[tid];
            float p = fmaf(ta.x, wb.x, fmaf(ta.y, wb.y, fmaf(ta.z, wb.z, ta.w * wb.w)));
#pragma unroll
            for (int o = 16; o; o >>= 1) p += __shfl_xor_sync(0xffffffffu, p, o);
            if (lane == 0) s_part[wid] = p;
            __syncthreads();
            if (tid == 0) {
                float s = 0.f;
#pragma unroll
                for (int w = 0; w < 8; w++) s += s_part[w];
                s_e[c] = __expf(s - mm);
            }
            __syncthreads();
        } else {
            if (tid == 0) s_e[c] = 0.0f;          // excluded: exact 0, bit-stable
            __syncthreads();
        }
    }

    if (tid < 16) {
        float s = 0.f;
        for (int c = 0; c < cnt; c++) {
            const float e = s_e[c];
            if (tid == NBITS) s += e;
            else if ((s_vcand[c] >> (NBITS - 1 - tid)) & 1) s += e;
        }
        sfin[tid] = s;
    }
    __syncthreads();
    if (tid < NBITS) {
        const float Zt = sfin[NBITS];
        logit_w[(size_t)row * NBITS + tid] = (2.f * sfin[tid] - Zt) / Zt;
    }
}

// ---------------- launch ----------------------------------------------------
extern "C" void kernel_launch(void* const* d_in, const int* in_sizes, int n_in,
                              void* d_out, int out_size)
{
    const int*   ids        = (const int*)  d_in[0];
    const float* tensor     = (const float*)d_in[1];
    const float* weight     = (const float*)d_in[2];
    const float* weight_bit = (const float*)d_in[3];

    float* out       = (float*)d_out;
    float* out_id    = out;
    float* out_bit   = out + (size_t)MDIM * KDIM;
    float* out_logit = out + (size_t)2 * MDIM * KDIM;
    float* out_lw    = out_logit + (size_t)MDIM * VOCABN;

    cudaFuncSetAttribute(gemm_kernel,
                         cudaFuncAttributeMaxDynamicSharedMemorySize, GEMM_SMEM);

    const int initN = (MDIM * NWORDS + 255) / 256;
    init_kernel<<<initN, 256>>>();
    embed_kernel<<<MDIM, 256>>>(ids, weight, weight_bit, out_id, out_bit);
    const int convN = NA_F4 + VOCABN * KDIM / 4;
    conv_kernel<<<(convN + 255) / 256, 256>>>(tensor, weight);

    dim3 grid(MDIM / BM, VOCABN / BN);  // M fastest -> B-slice L2 reuse
    gemm_kernel<<<grid, 256, GEMM_SMEM>>>(out_logit);

    softmax_bits_kernel<<<MDIM, 256>>>(out_logit, tensor, weight, out_lw);
}

// round 16
// speedup vs baseline: 1.2302x; 1.0604x over previous
#include <cuda_runtime.h>
#include <cuda_fp16.h>
#include <cstdint>
#include <math.h>
#include <float.h>

#define MDIM   4096
#define KDIM   1024
#define VOCABN 32000
#define NBITS  15
#define NWORDS (VOCABN / 32)            // 1000
#define MAXCAND 512

// ---------------- scratch ----------------------------------------------------
__device__ __half g_Ah[(size_t)MDIM * KDIM];
__device__ __half g_Bh[(size_t)VOCABN * KDIM];
__device__ uint32_t g_rowmax[MDIM];                 // monotone-uint fp32 row max
__device__ uint32_t g_bmap[(size_t)MDIM * NWORDS];  // candidate bitmap (16 MB)

__device__ __forceinline__ uint32_t smem_u32(const void* p) {
    uint32_t a;
    asm("{ .reg .u64 t; cvta.to.shared.u64 t, %1; cvt.u32.u64 %0, t; }"
        : "=r"(a) : "l"(p));
    return a;
}
#define SW128(o) ((o) ^ (((o) >> 3) & 0x70))

__device__ __forceinline__ uint32_t fkey(float f) {
    uint32_t u = __float_as_uint(f);
    return (u & 0x80000000u) ? ~u : (u | 0x80000000u);
}
__device__ __forceinline__ float fdec(uint32_t k) {
    return __uint_as_float((k & 0x80000000u) ? (k & 0x7fffffffu) : ~k);
}

// ---------------- init: zero bitmap + rowmax ---------------------------------
__global__ __launch_bounds__(256) void init_kernel() {
    const size_t i = (size_t)blockIdx.x * 256 + threadIdx.x;
    if (i < (size_t)MDIM * NWORDS) g_bmap[i] = 0u;
    if (i < MDIM) g_rowmax[i] = fkey(-FLT_MAX);
}

// ---------------- merged convert (f32 -> fp16) -------------------------------
#define NA_F4 (MDIM * KDIM / 4)
__global__ __launch_bounds__(256) void conv_kernel(
    const float* __restrict__ srcA, const float* __restrict__ srcB)
{
    const int i = blockIdx.x * 256 + threadIdx.x;
    const bool isA = (i < NA_F4);
    const int j = isA ? i : i - NA_F4;
    float4 v = isA ? ((const float4*)srcA)[j] : ((const float4*)srcB)[j];
    ushort4 h4;
    h4.x = __half_as_ushort(__float2half_rn(v.x));
    h4.y = __half_as_ushort(__float2half_rn(v.y));
    h4.z = __half_as_ushort(__float2half_rn(v.z));
    h4.w = __half_as_ushort(__float2half_rn(v.w));
    if (isA) ((ushort4*)g_Ah)[j] = h4; else ((ushort4*)g_Bh)[j] = h4;
}

// ---------------- embed: gather + bit combo ---------------------------------
__global__ __launch_bounds__(256) void embed_kernel(
    const int* __restrict__ ids, const float* __restrict__ weight,
    const float* __restrict__ weight_bit,
    float* __restrict__ out_id, float* __restrict__ out_bit)
{
    const int t = blockIdx.x;
    const int id = ids[t];
    const int d = threadIdx.x * 4;
    float4 w = *(const float4*)(weight + (size_t)id * KDIM + d);
    *(float4*)(out_id + (size_t)t * KDIM + d) = w;
    float4 acc = make_float4(0.f, 0.f, 0.f, 0.f);
#pragma unroll
    for (int j = 0; j < NBITS; j++) {
        const float s = ((id >> (NBITS - 1 - j)) & 1) ? 1.0f : -1.0f;
        float4 wb = *(const float4*)(weight_bit + j * KDIM + d);
        acc.x = fmaf(s, wb.x, acc.x); acc.y = fmaf(s, wb.y, acc.y);
        acc.z = fmaf(s, wb.z, acc.z); acc.w = fmaf(s, wb.w, acc.w);
    }
    *(float4*)(out_bit + (size_t)t * KDIM + d) = acc;
}

// ---------------- fp16 GEMM (fp32 acc) + marking epilogue --------------------
#define BM 128
#define BN 128
#define BK 64
#define NSTAGE 3
#define TILE_A (BM * BK * 2)
#define TILE_Bt (BN * BK * 2)
#define OFF_B TILE_A
#define STAGE_B (TILE_A + TILE_Bt)      // 32 KB
#define GEMM_SMEM (NSTAGE * STAGE_B)    // 96 KB

#define CP16(dst, src) \
    asm volatile("cp.async.cg.shared.global [%0], [%1], 16;" \
                 :: "r"(dst), "l"(src) : "memory")
#define LDSM4(r0, r1, r2, r3, a) \
    asm volatile("ldmatrix.sync.aligned.m8n8.x4.shared.b16 {%0,%1,%2,%3}, [%4];" \
                 : "=r"(r0), "=r"(r1), "=r"(r2), "=r"(r3) : "r"(a))
#define MMA16816(d, a, b0, b1) \
    asm volatile("mma.sync.aligned.m16n8k16.row.col.f32.f16.f16.f32 " \
                 "{%0,%1,%2,%3}, {%4,%5,%6,%7}, {%8,%9}, {%0,%1,%2,%3};" \
                 : "+f"((d)[0]), "+f"((d)[1]), "+f"((d)[2]), "+f"((d)[3]) \
                 : "r"((a)[0]), "r"((a)[1]), "r"((a)[2]), "r"((a)[3]), \
                   "r"(b0), "r"(b1))

__global__ __launch_bounds__(256, 2) void gemm_kernel(float* __restrict__ C)
{
    extern __shared__ char smem[];
    const uint32_t sb = smem_u32(smem);
    const int tid = threadIdx.x, wid = tid >> 5, lane = tid & 31;
    const int bm = blockIdx.x * BM, bn = blockIdx.y * BN;
    const int wm = (wid & 1) * 64;
    const int wn = (wid >> 1) * 32;

    const __half* gAh = g_Ah + (size_t)bm * KDIM;
    const __half* gBh = g_Bh + (size_t)bn * KDIM;

    const int NK = KDIM / BK;

    auto load_stage = [&](int kt, int stg) {
        const uint32_t base = sb + stg * STAGE_B;
        const int ke = kt * BK;
#pragma unroll
        for (int i = 0; i < 4; i++) {
            const int chunk = i * 256 + tid;
            const int row = chunk >> 3;
            const int kc = chunk & 7;
            const uint32_t d = SW128(row * 128 + kc * 16);
            const size_t so = (size_t)row * KDIM + ke + kc * 8;
            CP16(base + d,         gAh + so);
            CP16(base + OFF_B + d, gBh + so);
        }
        asm volatile("cp.async.commit_group;" ::: "memory");
    };

    load_stage(0, 0);
    load_stage(1, 1);

    float acc[4][4][4] = {};

    const int lrow = lane & 15;
    const int lkb  = (lane >> 4) * 16;
    int offA[4], offB[2];
#pragma unroll
    for (int mt = 0; mt < 4; mt++) offA[mt] = (wm + mt * 16 + lrow) * 128 + lkb;
#pragma unroll
    for (int nt = 0; nt < 2; nt++) offB[nt] = (wn + nt * 16 + lrow) * 128 + lkb;

    int stg = 0;
    for (int kt = 0; kt < NK; kt++) {
        asm volatile("cp.async.wait_group 1;" ::: "memory");
        __syncthreads();
        if (kt + 2 < NK) {
            int s2 = stg + 2; if (s2 >= NSTAGE) s2 -= NSTAGE;
            load_stage(kt + 2, s2);
        }
        const uint32_t base = sb + stg * STAGE_B;

#pragma unroll
        for (int ks = 0; ks < 4; ks++) {
            uint32_t ah[4][4];
#pragma unroll
            for (int mt = 0; mt < 4; mt++) {
                const uint32_t a = base + SW128(offA[mt] + ks * 32);
                LDSM4(ah[mt][0], ah[mt][1], ah[mt][2], ah[mt][3], a);
            }
            uint32_t b[2][4];
#pragma unroll
            for (int nt = 0; nt < 2; nt++) {
                const uint32_t ba = base + SW128(offB[nt] + ks * 32);
                LDSM4(b[nt][0], b[nt][1], b[nt][2], b[nt][3], ba + OFF_B);
            }
#pragma unroll
            for (int mt = 0; mt < 4; mt++)
#pragma unroll
                for (int nt = 0; nt < 2; nt++) {
                    MMA16816(acc[mt][2 * nt + 0], ah[mt], b[nt][0], b[nt][2]);
                    MMA16816(acc[mt][2 * nt + 1], ah[mt], b[nt][1], b[nt][3]);
                }
        }
        if (++stg >= NSTAGE) stg = 0;
    }

    // epilogue: stores + running row max + candidate marking (superset)
    const int er = lane >> 2, ec = (lane & 3) * 2;
#pragma unroll
    for (int mt = 0; mt < 4; mt++) {
        const int row0 = bm + wm + mt * 16 + er;
        const int row1 = row0 + 8;
        float r0 = -FLT_MAX, r1 = -FLT_MAX;
#pragma unroll
        for (int j = 0; j < 4; j++) {
            float* c0 = C + (size_t)row0 * VOCABN + bn + wn + j * 8 + ec;
            *(float2*)c0 = make_float2(acc[mt][j][0], acc[mt][j][1]);
            float* c1 = C + (size_t)row1 * VOCABN + bn + wn + j * 8 + ec;
            *(float2*)c1 = make_float2(acc[mt][j][2], acc[mt][j][3]);
            r0 = fmaxf(r0, fmaxf(acc[mt][j][0], acc[mt][j][1]));
            r1 = fmaxf(r1, fmaxf(acc[mt][j][2], acc[mt][j][3]));
        }
        r0 = fmaxf(r0, __shfl_xor_sync(0xffffffffu, r0, 1));
        r0 = fmaxf(r0, __shfl_xor_sync(0xffffffffu, r0, 2));
        r1 = fmaxf(r1, __shfl_xor_sync(0xffffffffu, r1, 1));
        r1 = fmaxf(r1, __shfl_xor_sync(0xffffffffu, r1, 2));
        uint32_t run0 = 0u, run1 = 0u;
        if ((lane & 3) == 0) {
            uint32_t o0 = atomicMax(&g_rowmax[row0], fkey(r0));
            uint32_t o1 = atomicMax(&g_rowmax[row1], fkey(r1));
            run0 = (o0 > fkey(r0)) ? o0 : fkey(r0);
            run1 = (o1 > fkey(r1)) ? o1 : fkey(r1);
        }
        run0 = __shfl_sync(0xffffffffu, run0, lane & ~3);
        run1 = __shfl_sync(0xffffffffu, run1, lane & ~3);
        const float t0 = fdec(run0) - 20.0f;
        const float t1 = fdec(run1) - 20.0f;
#pragma unroll
        for (int j = 0; j < 4; j++) {
            const int col = bn + wn + j * 8 + ec;
            if (acc[mt][j][0] > t0)
                atomicOr(&g_bmap[(size_t)row0 * NWORDS + (col >> 5)], 1u << (col & 31));
            if (acc[mt][j][1] > t0)
                atomicOr(&g_bmap[(size_t)row0 * NWORDS + ((col + 1) >> 5)], 1u << ((col + 1) & 31));
            if (acc[mt][j][2] > t1)
                atomicOr(&g_bmap[(size_t)row1 * NWORDS + (col >> 5)], 1u << (col & 31));
            if (acc[mt][j][3] > t1)
                atomicOr(&g_bmap[(size_t)row1 * NWORDS + ((col + 1) >> 5)], 1u << ((col + 1) & 31));
        }
    }
}

// ---------------- softmax from bitmap, warp-parallel exact dots -------------
// Candidate c is owned by warp (c & 7); each warp computes the full exact
// fp32 dot itself (32 elems/lane in registers, fixed-order reduction) -> no
// block syncs in the candidate loop. Non-survivors of the final-max re-filter
// write exact 0.0f (additive identity) so superset variation is bit-stable.
__global__ __launch_bounds__(256) void softmax_bits_kernel(
    const float* __restrict__ logit, const float* __restrict__ tensor,
    const float* __restrict__ weight, float* __restrict__ logit_w)
{
    const int row = blockIdx.x;
    const int tid = threadIdx.x;
    const int lane = tid & 31, wid = tid >> 5;

    __shared__ int s_vcand[MAXCAND];
    __shared__ int s_count;
    __shared__ float s_e[MAXCAND];
    __shared__ float sfin[16];

    const float mm = fdec(g_rowmax[row]);
    const float thr = mm - 20.0f;
    const uint32_t* bmap = g_bmap + (size_t)row * NWORDS;

    // per-lane slice of tensor row: columns [lane*32, lane*32+32)
    const float4* t4 = (const float4*)(tensor + (size_t)row * KDIM);
    float4 ta[8];
#pragma unroll
    for (int q = 0; q < 8; q++) ta[q] = t4[lane * 8 + q];

    // warp 0: compact marked bits (ascending vv)
    if (wid == 0) {
        const int w0 = lane * 32;
        int cnt = 0;
        for (int w = w0; w < w0 + 32 && w < NWORDS; w++) cnt += __popc(bmap[w]);
        int pre = cnt;
#pragma unroll
        for (int o = 1; o < 32; o <<= 1) {
            int n = __shfl_up_sync(0xffffffffu, pre, o);
            if (lane >= o) pre += n;
        }
        if (lane == 31) s_count = (pre < MAXCAND) ? pre : MAXCAND;
        int idx = pre - cnt;
        for (int w = w0; w < w0 + 32 && w < NWORDS; w++) {
            uint32_t bits = bmap[w];
            while (bits) {
                const int b = __ffs(bits) - 1;
                bits &= bits - 1;
                if (idx < MAXCAND) s_vcand[idx] = w * 32 + b;
                idx++;
            }
        }
    }
    __syncthreads();
    const int cnt = s_count;

    // warp-parallel exact dots (candidate c -> warp c&7), no block syncs
    for (int c = wid; c < cnt; c += 8) {
        const int vv = s_vcand[c];
        const float lg = logit[(size_t)row * VOCABN + vv];
        float e = 0.0f;
        if (lg > thr) {
            const float4* w4 = (const float4*)(weight + (size_t)vv * KDIM);
            float s0 = 0.f, s1 = 0.f, s2 = 0.f, s3 = 0.f;
#pragma unroll
            for (int q = 0; q < 8; q++) {
                float4 b = w4[lane * 8 + q];
                s0 = fmaf(ta[q].x, b.x, s0); s1 = fmaf(ta[q].y, b.y, s1);
                s2 = fmaf(ta[q].z, b.z, s2); s3 = fmaf(ta[q].w, b.w, s3);
            }
            float p = (s0 + s1) + (s2 + s3);
#pragma unroll
            for (int o = 16; o; o >>= 1) p += __shfl_xor_sync(0xffffffffu, p, o);
            e = __expf(p - mm);
        }
        if (lane == 0) s_e[c] = e;
    }
    __syncthreads();

    // final sums over ascending candidate list (deterministic)
    if (tid < 16) {
        float s = 0.f;
        for (int c = 0; c < cnt; c++) {
            const float e = s_e[c];
            if (tid == NBITS) s += e;
            else if ((s_vcand[c] >> (NBITS - 1 - tid)) & 1) s += e;
        }
        sfin[tid] = s;
    }
    __syncthreads();
    if (tid < NBITS) {
        const float Zt = sfin[NBITS];
        logit_w[(size_t)row * NBITS + tid] = (2.f * sfin[tid] - Zt) / Zt;
    }
}

// ---------------- launch ----------------------------------------------------
extern "C" void kernel_launch(void* const* d_in, const int* in_sizes, int n_in,
                              void* d_out, int out_size)
{
    const int*   ids        = (const int*)  d_in[0];
    const float* tensor     = (const float*)d_in[1];
    const float* weight     = (const float*)d_in[2];
    const float* weight_bit = (const float*)d_in[3];

    float* out       = (float*)d_out;
    float* out_id    = out;
    float* out_bit   = out + (size_t)MDIM * KDIM;
    float* out_logit = out + (size_t)2 * MDIM * KDIM;
    float* out_lw    = out_logit + (size_t)MDIM * VOCABN;

    cudaFuncSetAttribute(gemm_kernel,
                         cudaFuncAttributeMaxDynamicSharedMemorySize, GEMM_SMEM);

    const int initN = (MDIM * NWORDS + 255) / 256;
    init_kernel<<<initN, 256>>>();
    embed_kernel<<<MDIM, 256>>>(ids, weight, weight_bit, out_id, out_bit);
    const int convN = NA_F4 + VOCABN * KDIM / 4;
    conv_kernel<<<(convN + 255) / 256, 256>>>(tensor, weight);

    dim3 grid(MDIM / BM, VOCABN / BN);  // M fastest -> B-slice L2 reuse
    gemm_kernel<<<grid, 256, GEMM_SMEM>>>(out_logit);

    softmax_bits_kernel<<<MDIM, 256>>>(out_logit, tensor, weight, out_lw);
}